// round 5
// baseline (speedup 1.0000x reference)
#include <cuda_runtime.h>

// nck with common-denominator trick: 3 EX2 + 1 RCP (MUFU) instead of 3 EX2 + 3 RCP.
// Clamp z >= -160: below that the true value is ~0 but the combined denominator
// d1*d2*d3 would overflow fp32 (~3e39 at z=-180); at -160 den ~1.1e35, safe.
__device__ __forceinline__ float nck_f(float z, float ca, float cb, float cg)
{
    z = fmaxf(z, -160.0f);
    float e1 = __expf(fmaf(z, -0.11135857461024499f, 6.39f));   // 6.39 - z/8.98
    float e2 = __expf(fmaf(z, -0.23529411764705882f, -4.4f));   // -4.4 - z/4.25
    float e3 = __expf(fmaf(z, -0.132f, 2.20968f));              // -0.132*(z-16.74)
    float d1 = 1.0f + e1;
    float d2 = 1.0f + e2;
    float d3 = 0.436f + e3;
    float n1 = ca * (z - 113.68f);
    float n2 = cb * (z - 69.62f);
    float d12 = d1 * d2;
    float num = fmaf(fmaf(n1, d2, n2 * d1), d3, cg * d12);
    float den = d12 * d3;
    return __fdividef(num, den);
}

__global__ __launch_bounds__(256) void tree_kernel(
    const float* __restrict__ x, float* __restrict__ out,
    const float* __restrict__ w0, const float* __restrict__ w1,
    const float* __restrict__ w2, const float* __restrict__ w3,
    const float* __restrict__ w4, const float* __restrict__ w5,
    const float* __restrict__ w6, const float* __restrict__ w7,
    const float* __restrict__ w8,
    const float* __restrict__ b0, const float* __restrict__ b1,
    const float* __restrict__ b2, const float* __restrict__ b3,
    const float* __restrict__ b4, const float* __restrict__ b5,
    const float* __restrict__ b6, const float* __restrict__ b7,
    const float* __restrict__ b8,
    const float* __restrict__ alpha, const float* __restrict__ beta,
    const float* __restrict__ gamma, const float* __restrict__ root_w,
    const float* __restrict__ root_b,
    int rows, int warp_stride)
{
    // Permutation-folded parameter tables, built per block in shared memory.
    // Canonical recurrence (triple-verified against reference semantics):
    //   V_l[k] = nck( w_l[2t+1]*V_{l-1}[2k] + w_l[2t]*V_{l-1}[2k+1] + b_l[C-1+t] ),
    //   t = k ^ (0xAA & (C-1)),  C = 256 >> l;  leaf: p = k^0xAA,
    //   V_0[k] = nck(w0[p]*x[255-p] + b0[255+p]);  out = sigmoid(rw*V_8[0]+rb).
    __shared__ float  s_leafW[256];
    __shared__ float  s_leafB[256];
    __shared__ float4 s_lvl[256];   // levels 1..8: off(l) = 256-2C
                                    // entry k: {w[2t+1], w[2t], b[C-1+t], 0}
    {
        int k = threadIdx.x;                 // 0..255
        int p0 = k ^ 0xAA;
        s_leafW[k] = w0[p0];
        s_leafB[k] = b0[255 + p0];
        const float* W[8] = {w1, w2, w3, w4, w5, w6, w7, w8};
        const float* B[8] = {b1, b2, b3, b4, b5, b6, b7, b8};
#pragma unroll
        for (int l = 1; l <= 8; ++l) {
            int C = 256 >> l;
            if (k < C) {
                int t = k ^ (0xAA & (C - 1));
                s_lvl[256 - 2 * C + k] =
                    make_float4(W[l-1][2*t + 1], W[l-1][2*t], B[l-1][C - 1 + t], 0.0f);
            }
        }
    }
    __syncthreads();

    float ca = __ldg(alpha) * 0.0878f;
    float cb = __ldg(beta)  * 0.129f;
    float cg = __ldg(gamma) * 2.23f;
    float rw = __ldg(root_w);
    float rb = __ldg(root_b);

    int lane  = threadIdx.x & 31;
    int warp0 = blockIdx.x * (blockDim.x >> 5) + (threadIdx.x >> 5);

    // ---- Hoist ALL row-invariant parameters into registers ----
    const float4* lwv = reinterpret_cast<const float4*>(s_leafW);
    const float4* lbv = reinterpret_cast<const float4*>(s_leafB);
    float4 wa = lwv[2*lane], wb = lwv[2*lane + 1];
    float4 ba = lbv[2*lane], bb = lbv[2*lane + 1];
    float4 p1a = s_lvl[4*lane + 0], p1b = s_lvl[4*lane + 1];
    float4 p1c = s_lvl[4*lane + 2], p1d = s_lvl[4*lane + 3];
    float4 p2a = s_lvl[128 + 2*lane], p2b = s_lvl[128 + 2*lane + 1];
    float4 p3  = s_lvl[192 + lane];
    float4 p4 = s_lvl[224 + (lane & 15)];
    float4 p5 = s_lvl[240 + (lane & 7)];
    float4 p6 = s_lvl[248 + (lane & 3)];
    float4 p7 = s_lvl[252 + (lane & 1)];
    float4 p8 = s_lvl[254];
    int c = 31 - (lane ^ 21);   // x chunk for this lane (8 floats)

    if (warp0 >= rows) return;

    // Software pipeline: preload first row's x.
    const float4* xr = reinterpret_cast<const float4*>(x + (size_t)warp0 * 256);
    float4 lo = __ldg(&xr[2*c]);
    float4 hi = __ldg(&xr[2*c + 1]);

    for (int row = warp0; row < rows; row += warp_stride) {
        // ---- Level 0: elem per i = {5,4,7,6,1,0,3,2} -> vector lanes below
        float v0 = nck_f(fmaf(wa.x, hi.y, ba.x), ca, cb, cg);
        float v1 = nck_f(fmaf(wa.y, hi.x, ba.y), ca, cb, cg);
        float v2 = nck_f(fmaf(wa.z, hi.w, ba.z), ca, cb, cg);
        float v3 = nck_f(fmaf(wa.w, hi.z, ba.w), ca, cb, cg);
        float v4 = nck_f(fmaf(wb.x, lo.y, bb.x), ca, cb, cg);
        float v5 = nck_f(fmaf(wb.y, lo.x, bb.y), ca, cb, cg);
        float v6 = nck_f(fmaf(wb.z, lo.w, bb.z), ca, cb, cg);
        float v7 = nck_f(fmaf(wb.w, lo.z, bb.w), ca, cb, cg);

        // ---- Level 1
        float u0 = nck_f(fmaf(p1a.x, v0, fmaf(p1a.y, v1, p1a.z)), ca, cb, cg);
        float u1 = nck_f(fmaf(p1b.x, v2, fmaf(p1b.y, v3, p1b.z)), ca, cb, cg);
        float u2 = nck_f(fmaf(p1c.x, v4, fmaf(p1c.y, v5, p1c.z)), ca, cb, cg);
        float u3 = nck_f(fmaf(p1d.x, v6, fmaf(p1d.y, v7, p1d.z)), ca, cb, cg);

        // ---- Level 2
        float s0 = nck_f(fmaf(p2a.x, u0, fmaf(p2a.y, u1, p2a.z)), ca, cb, cg);
        float s1 = nck_f(fmaf(p2b.x, u2, fmaf(p2b.y, u3, p2b.z)), ca, cb, cg);

        // ---- Level 3
        float val = nck_f(fmaf(p3.x, s0, fmaf(p3.y, s1, p3.z)), ca, cb, cg);

        // ---- Prefetch next row's x under the serial shuffle tail ----
        int next = row + warp_stride;
        if (next < rows) {
            const float4* xn = reinterpret_cast<const float4*>(x + (size_t)next * 256);
            lo = __ldg(&xn[2*c]);
            hi = __ldg(&xn[2*c + 1]);
        }

        // ---- Levels 4..8 via warp shuffles (lanes >= C compute wrapped dups)
        {
            float a0 = __shfl_sync(0xffffffffu, val, (2*lane)     & 31);
            float a1 = __shfl_sync(0xffffffffu, val, (2*lane + 1) & 31);
            val = nck_f(fmaf(p4.x, a0, fmaf(p4.y, a1, p4.z)), ca, cb, cg);
        }
        {
            float a0 = __shfl_sync(0xffffffffu, val, (2*lane)     & 31);
            float a1 = __shfl_sync(0xffffffffu, val, (2*lane + 1) & 31);
            val = nck_f(fmaf(p5.x, a0, fmaf(p5.y, a1, p5.z)), ca, cb, cg);
        }
        {
            float a0 = __shfl_sync(0xffffffffu, val, (2*lane)     & 31);
            float a1 = __shfl_sync(0xffffffffu, val, (2*lane + 1) & 31);
            val = nck_f(fmaf(p6.x, a0, fmaf(p6.y, a1, p6.z)), ca, cb, cg);
        }
        {
            float a0 = __shfl_sync(0xffffffffu, val, (2*lane)     & 31);
            float a1 = __shfl_sync(0xffffffffu, val, (2*lane + 1) & 31);
            val = nck_f(fmaf(p7.x, a0, fmaf(p7.y, a1, p7.z)), ca, cb, cg);
        }
        {
            float a0 = __shfl_sync(0xffffffffu, val, (2*lane)     & 31);
            float a1 = __shfl_sync(0xffffffffu, val, (2*lane + 1) & 31);
            val = nck_f(fmaf(p8.x, a0, fmaf(p8.y, a1, p8.z)), ca, cb, cg);
        }

        if (lane == 0) {
            float o = fmaf(rw, val, rb);
            out[row] = __fdividef(1.0f, 1.0f + __expf(-o));
        }
    }
}

extern "C" void kernel_launch(void* const* d_in, const int* in_sizes, int n_in,
                              void* d_out, int out_size)
{
    // Grouped order: x, w0..w8, b0..b8, alpha, beta, gamma, root_w, root_b.
    // setup_inputs() dict order is interleaved (x, w0, b0, w1, b1, ...).
    // Disambiguate via sizes: b vectors have 511 elems (w1 has 256).
    // Scalars land at indices 19..23 in BOTH orders.
    const float* x = (const float*)d_in[0];
    const float* w[9];
    const float* b[9];
    if (n_in >= 3 && in_sizes[2] == 511) {
        for (int l = 0; l < 9; ++l) { w[l] = (const float*)d_in[1 + 2*l];
                                      b[l] = (const float*)d_in[2 + 2*l]; }
    } else {
        for (int l = 0; l < 9; ++l) { w[l] = (const float*)d_in[1 + l];
                                      b[l] = (const float*)d_in[10 + l]; }
    }
    const float* alpha  = (const float*)d_in[19];
    const float* beta   = (const float*)d_in[20];
    const float* gammap = (const float*)d_in[21];
    const float* root_w = (const float*)d_in[22];
    const float* root_b = (const float*)d_in[23];
    float* out = (float*)d_out;

    int rows = in_sizes[0] / 256;          // 32768
    int warps_per_block = 256 / 32;        // 8
    int nblocks = 1024;                    // grid-stride: 4 rows per warp
    int total_warps = nblocks * warps_per_block;
    if (total_warps > rows) {              // safety for smaller shapes
        nblocks = (rows + warps_per_block - 1) / warps_per_block;
        total_warps = nblocks * warps_per_block;
    }

    tree_kernel<<<nblocks, 256>>>(
        x, out,
        w[0], w[1], w[2], w[3], w[4], w[5], w[6], w[7], w[8],
        b[0], b[1], b[2], b[3], b[4], b[5], b[6], b[7], b[8],
        alpha, beta, gammap, root_w, root_b,
        rows, total_warps);
}

// round 9
// speedup vs baseline: 1.3975x; 1.3975x over previous
#include <cuda_runtime.h>

__device__ __forceinline__ float ex2f(float x)
{
    float r;
    asm("ex2.approx.ftz.f32 %0, %1;" : "=f"(r) : "f"(x));
    return r;
}

// nck, common-denominator form: 3 EX2 + 1 RCP (MUFU), log2e pre-folded into
// the fma constants (no FMUL-by-log2e per exp).
// Clamp z >= -160: den peaks ~1.2e35 < fp32 max; below the clamp true value ~0.
__device__ __forceinline__ float nck_f(float z, float ca, float cb, float cg)
{
    z = fmaxf(z, -160.0f);
    float e1 = ex2f(fmaf(z, -0.16065646335066408f,  9.2188213112804756f)); // log2e*(6.39 - z/8.98)
    float e2 = ex2f(fmaf(z, -0.33945765667975613f, -6.3478581799114390f)); // log2e*(-4.4 - z/4.25)
    float e3 = ex2f(fmaf(z, -0.19043574539734317f,  3.1878943781547330f)); // log2e*(-0.132z + 2.20968)
    float d1 = 1.0f + e1;
    float d2 = 1.0f + e2;
    float d3 = 0.436f + e3;
    float n1 = ca * (z - 113.68f);
    float n2 = cb * (z - 69.62f);
    float d12 = d1 * d2;
    float num = fmaf(fmaf(n1, d2, n2 * d1), d3, cg * d12);
    return __fdividef(num, d12 * d3);
}

__global__ __launch_bounds__(256, 2) void tree_kernel(
    const float* __restrict__ x, float* __restrict__ out,
    const float* __restrict__ w0, const float* __restrict__ w1,
    const float* __restrict__ w2, const float* __restrict__ w3,
    const float* __restrict__ w4, const float* __restrict__ w5,
    const float* __restrict__ w6, const float* __restrict__ w7,
    const float* __restrict__ w8,
    const float* __restrict__ b0, const float* __restrict__ b1,
    const float* __restrict__ b2, const float* __restrict__ b3,
    const float* __restrict__ b4, const float* __restrict__ b5,
    const float* __restrict__ b6, const float* __restrict__ b7,
    const float* __restrict__ b8,
    const float* __restrict__ alpha, const float* __restrict__ beta,
    const float* __restrict__ gamma, const float* __restrict__ root_w,
    const float* __restrict__ root_b,
    int rows, int warp_stride)
{
    // Canonical recurrence (verified, bit-exact vs reference):
    //   V_l[k] = nck( w_l[2t+1]*V_{l-1}[2k] + w_l[2t]*V_{l-1}[2k+1] + b_l[C-1+t] ),
    //   t = k ^ (0xAA & (C-1)), C = 256>>l; leaf p = k^0xAA,
    //   V_0[k] = nck(w0[p]*x[255-p] + b0[255+p]); out = sigmoid(rw*V_8[0]+rb).
    __shared__ float  s_leafW[256];
    __shared__ float  s_leafB[256];
    __shared__ float4 s_lvl[256];   // levels 1..8: off(l)=256-2C; {w[2t+1],w[2t],b[C-1+t],0}
    {
        int k = threadIdx.x;
        int p0 = k ^ 0xAA;
        s_leafW[k] = w0[p0];
        s_leafB[k] = b0[255 + p0];
        const float* W[8] = {w1, w2, w3, w4, w5, w6, w7, w8};
        const float* B[8] = {b1, b2, b3, b4, b5, b6, b7, b8};
#pragma unroll
        for (int l = 1; l <= 8; ++l) {
            int C = 256 >> l;
            if (k < C) {
                int t = k ^ (0xAA & (C - 1));
                s_lvl[256 - 2 * C + k] =
                    make_float4(W[l-1][2*t + 1], W[l-1][2*t], B[l-1][C - 1 + t], 0.0f);
            }
        }
    }
    __syncthreads();

    float ca = __ldg(alpha) * 0.0878f;
    float cb = __ldg(beta)  * 0.129f;
    float cg = __ldg(gamma) * 2.23f;
    float rw = __ldg(root_w);
    float rb = __ldg(root_b);

    int lane   = threadIdx.x & 31;
    int warp0  = blockIdx.x * (blockDim.x >> 5) + (threadIdx.x >> 5);
    int c      = 31 - (lane ^ 21);          // x chunk for this lane
    bool loHalf = (lane < 16);

    const float4* lwv = reinterpret_cast<const float4*>(s_leafW);
    const float4* lbv = reinterpret_cast<const float4*>(s_leafB);

    if (warp0 >= rows) return;
    const int S = warp_stride;

    // Preload first pair (rowB clamped for safety; store is guarded).
    float4 loA, hiA, loB, hiB;
    {
        int rA = warp0;
        int rB = (warp0 + S < rows) ? warp0 + S : rows - 1;
        const float4* xa = reinterpret_cast<const float4*>(x + (size_t)rA * 256);
        const float4* xb = reinterpret_cast<const float4*>(x + (size_t)rB * 256);
        loA = __ldg(&xa[2*c]); hiA = __ldg(&xa[2*c + 1]);
        loB = __ldg(&xb[2*c]); hiB = __ldg(&xb[2*c + 1]);
    }

    for (int row = warp0; row < rows; row += 2 * S) {
        // ---- Level 0 (both rows share leaf params; elem map {hi.y,hi.x,hi.w,hi.z,lo.y,lo.x,lo.w,lo.z})
        float4 wa = lwv[2*lane], wb = lwv[2*lane + 1];
        float4 ba = lbv[2*lane], bb = lbv[2*lane + 1];

        float vA0 = nck_f(fmaf(wa.x, hiA.y, ba.x), ca, cb, cg);
        float vA1 = nck_f(fmaf(wa.y, hiA.x, ba.y), ca, cb, cg);
        float vA2 = nck_f(fmaf(wa.z, hiA.w, ba.z), ca, cb, cg);
        float vA3 = nck_f(fmaf(wa.w, hiA.z, ba.w), ca, cb, cg);
        float vA4 = nck_f(fmaf(wb.x, loA.y, bb.x), ca, cb, cg);
        float vA5 = nck_f(fmaf(wb.y, loA.x, bb.y), ca, cb, cg);
        float vA6 = nck_f(fmaf(wb.z, loA.w, bb.z), ca, cb, cg);
        float vA7 = nck_f(fmaf(wb.w, loA.z, bb.w), ca, cb, cg);

        float vB0 = nck_f(fmaf(wa.x, hiB.y, ba.x), ca, cb, cg);
        float vB1 = nck_f(fmaf(wa.y, hiB.x, ba.y), ca, cb, cg);
        float vB2 = nck_f(fmaf(wa.z, hiB.w, ba.z), ca, cb, cg);
        float vB3 = nck_f(fmaf(wa.w, hiB.z, ba.w), ca, cb, cg);
        float vB4 = nck_f(fmaf(wb.x, loB.y, bb.x), ca, cb, cg);
        float vB5 = nck_f(fmaf(wb.y, loB.x, bb.y), ca, cb, cg);
        float vB6 = nck_f(fmaf(wb.z, loB.w, bb.z), ca, cb, cg);
        float vB7 = nck_f(fmaf(wb.w, loB.z, bb.w), ca, cb, cg);

        // ---- Prefetch next pair's x (hidden under levels 1..8)
        {
            int nA = row + 2 * S;
            if (nA < rows) {
                int nB = (nA + S < rows) ? nA + S : rows - 1;
                const float4* xa = reinterpret_cast<const float4*>(x + (size_t)nA * 256);
                const float4* xb = reinterpret_cast<const float4*>(x + (size_t)nB * 256);
                loA = __ldg(&xa[2*c]); hiA = __ldg(&xa[2*c + 1]);
                loB = __ldg(&xb[2*c]); hiB = __ldg(&xb[2*c + 1]);
            }
        }

        // ---- Level 1
        float4 p;
        p = s_lvl[4*lane + 0];
        float uA0 = nck_f(fmaf(p.x, vA0, fmaf(p.y, vA1, p.z)), ca, cb, cg);
        float uB0 = nck_f(fmaf(p.x, vB0, fmaf(p.y, vB1, p.z)), ca, cb, cg);
        p = s_lvl[4*lane + 1];
        float uA1 = nck_f(fmaf(p.x, vA2, fmaf(p.y, vA3, p.z)), ca, cb, cg);
        float uB1 = nck_f(fmaf(p.x, vB2, fmaf(p.y, vB3, p.z)), ca, cb, cg);
        p = s_lvl[4*lane + 2];
        float uA2 = nck_f(fmaf(p.x, vA4, fmaf(p.y, vA5, p.z)), ca, cb, cg);
        float uB2 = nck_f(fmaf(p.x, vB4, fmaf(p.y, vB5, p.z)), ca, cb, cg);
        p = s_lvl[4*lane + 3];
        float uA3 = nck_f(fmaf(p.x, vA6, fmaf(p.y, vA7, p.z)), ca, cb, cg);
        float uB3 = nck_f(fmaf(p.x, vB6, fmaf(p.y, vB7, p.z)), ca, cb, cg);

        // ---- Level 2
        p = s_lvl[128 + 2*lane];
        float sA0 = nck_f(fmaf(p.x, uA0, fmaf(p.y, uA1, p.z)), ca, cb, cg);
        float sB0 = nck_f(fmaf(p.x, uB0, fmaf(p.y, uB1, p.z)), ca, cb, cg);
        p = s_lvl[128 + 2*lane + 1];
        float sA1 = nck_f(fmaf(p.x, uA2, fmaf(p.y, uA3, p.z)), ca, cb, cg);
        float sB1 = nck_f(fmaf(p.x, uB2, fmaf(p.y, uB3, p.z)), ca, cb, cg);

        // ---- Level 3: valA/valB = V3[lane] in all 32 lanes
        p = s_lvl[192 + lane];
        float valA = nck_f(fmaf(p.x, sA0, fmaf(p.y, sA1, p.z)), ca, cb, cg);
        float valB = nck_f(fmaf(p.x, sB0, fmaf(p.y, sB1, p.z)), ca, cb, cg);

        // ---- Level 4: pack rows. Lanes 0-15 -> row A V4[lane], lanes 16-31 -> row B V4[lane-16].
        int src0 = (2*lane) & 31, src1 = (2*lane + 1) & 31;
        float a0A = __shfl_sync(0xffffffffu, valA, src0);
        float a1A = __shfl_sync(0xffffffffu, valA, src1);
        float a0B = __shfl_sync(0xffffffffu, valB, src0);
        float a1B = __shfl_sync(0xffffffffu, valB, src1);
        float in0 = loHalf ? a0A : a0B;
        float in1 = loHalf ? a1A : a1B;
        p = s_lvl[224 + (lane & 15)];
        float val = nck_f(fmaf(p.x, in0, fmaf(p.y, in1, p.z)), ca, cb, cg);

        // ---- Levels 5..8: packed halves advance with the standard pattern.
        //  After level 5: lanes 0-7 = A, 8-15 = B; after 6: 0-3 = A, 4-7 = B; etc.
        {
            float t0 = __shfl_sync(0xffffffffu, val, src0);
            float t1 = __shfl_sync(0xffffffffu, val, src1);
            p = s_lvl[240 + (lane & 7)];
            val = nck_f(fmaf(p.x, t0, fmaf(p.y, t1, p.z)), ca, cb, cg);
        }
        {
            float t0 = __shfl_sync(0xffffffffu, val, src0);
            float t1 = __shfl_sync(0xffffffffu, val, src1);
            p = s_lvl[248 + (lane & 3)];
            val = nck_f(fmaf(p.x, t0, fmaf(p.y, t1, p.z)), ca, cb, cg);
        }
        {
            float t0 = __shfl_sync(0xffffffffu, val, src0);
            float t1 = __shfl_sync(0xffffffffu, val, src1);
            p = s_lvl[252 + (lane & 1)];
            val = nck_f(fmaf(p.x, t0, fmaf(p.y, t1, p.z)), ca, cb, cg);
        }
        {
            float t0 = __shfl_sync(0xffffffffu, val, src0);
            float t1 = __shfl_sync(0xffffffffu, val, src1);
            p = s_lvl[254];
            val = nck_f(fmaf(p.x, t0, fmaf(p.y, t1, p.z)), ca, cb, cg);
        }
        // Root of row A in lane 0, row B in lane 1.
        float o   = fmaf(rw, val, rb);
        float sig = __fdividef(1.0f, 1.0f + ex2f(-1.4426950408889634f * o));
        if (lane == 0) out[row] = sig;
        else if (lane == 1 && row + S < rows) out[row + S] = sig;
    }
}

extern "C" void kernel_launch(void* const* d_in, const int* in_sizes, int n_in,
                              void* d_out, int out_size)
{
    // Grouped order: x, w0..w8, b0..b8, scalars. Interleaved order (dict):
    // x, w0, b0, w1, b1, ... Disambiguate via sizes (b has 511 elems).
    const float* x = (const float*)d_in[0];
    const float* w[9];
    const float* b[9];
    if (n_in >= 3 && in_sizes[2] == 511) {
        for (int l = 0; l < 9; ++l) { w[l] = (const float*)d_in[1 + 2*l];
                                      b[l] = (const float*)d_in[2 + 2*l]; }
    } else {
        for (int l = 0; l < 9; ++l) { w[l] = (const float*)d_in[1 + l];
                                      b[l] = (const float*)d_in[10 + l]; }
    }
    const float* alpha  = (const float*)d_in[19];
    const float* beta   = (const float*)d_in[20];
    const float* gammap = (const float*)d_in[21];
    const float* root_w = (const float*)d_in[22];
    const float* root_b = (const float*)d_in[23];
    float* out = (float*)d_out;

    int rows = in_sizes[0] / 256;          // 32768
    int warps_per_block = 256 / 32;        // 8
    int nblocks = 1024;                    // 8192 warps, 2 row-pairs per warp
    int total_warps = nblocks * warps_per_block;
    if (total_warps > rows) {
        nblocks = (rows + warps_per_block - 1) / warps_per_block;
        total_warps = nblocks * warps_per_block;
    }

    tree_kernel<<<nblocks, 256>>>(
        x, out,
        w[0], w[1], w[2], w[3], w[4], w[5], w[6], w[7], w[8],
        b[0], b[1], b[2], b[3], b[4], b[5], b[6], b[7], b[8],
        alpha, beta, gammap, root_w, root_b,
        rows, total_warps);
}

// round 10
// speedup vs baseline: 1.4623x; 1.0464x over previous
#include <cuda_runtime.h>

__device__ __forceinline__ float ex2f(float x)
{
    float r;
    asm("ex2.approx.ftz.f32 %0, %1;" : "=f"(r) : "f"(x));
    return r;
}

// nck, common-denominator form: 3 EX2 + 1 RCP (MUFU), log2e pre-folded into
// the exp-arg constants; numerator affine terms pre-folded into FMAs.
// Clamp z >= -160: den peaks ~1.2e35 < fp32 max; below the clamp true value ~0.
__device__ __forceinline__ float nck_f(float z, float ca, float cb, float cg,
                                       float ca_c, float cb_c)
{
    z = fmaxf(z, -160.0f);
    float e1 = ex2f(fmaf(z, -0.16065646335066408f,  9.2188213112804756f)); // log2e*(6.39 - z/8.98)
    float e2 = ex2f(fmaf(z, -0.33945765667975613f, -6.3478581799114390f)); // log2e*(-4.4 - z/4.25)
    float e3 = ex2f(fmaf(z, -0.19043574539734317f,  3.1878943781547330f)); // log2e*(-0.132z + 2.20968)
    float d1 = 1.0f + e1;
    float d2 = 1.0f + e2;
    float d3 = 0.436f + e3;
    float n1 = fmaf(ca, z, ca_c);   // ca*(z - 113.68)
    float n2 = fmaf(cb, z, cb_c);   // cb*(z - 69.62)
    float d12 = d1 * d2;
    float num = fmaf(fmaf(n1, d2, n2 * d1), d3, cg * d12);
    return __fdividef(num, d12 * d3);
}

__global__ __launch_bounds__(256, 3) void tree_kernel(
    const float* __restrict__ x, float* __restrict__ out,
    const float* __restrict__ w0, const float* __restrict__ w1,
    const float* __restrict__ w2, const float* __restrict__ w3,
    const float* __restrict__ w4, const float* __restrict__ w5,
    const float* __restrict__ w6, const float* __restrict__ w7,
    const float* __restrict__ w8,
    const float* __restrict__ b0, const float* __restrict__ b1,
    const float* __restrict__ b2, const float* __restrict__ b3,
    const float* __restrict__ b4, const float* __restrict__ b5,
    const float* __restrict__ b6, const float* __restrict__ b7,
    const float* __restrict__ b8,
    const float* __restrict__ alpha, const float* __restrict__ beta,
    const float* __restrict__ gamma, const float* __restrict__ root_w,
    const float* __restrict__ root_b,
    int rows, int warp_stride)
{
    // Canonical recurrence (verified, bit-exact vs reference):
    //   V_l[k] = nck( w_l[2t+1]*V_{l-1}[2k] + w_l[2t]*V_{l-1}[2k+1] + b_l[C-1+t] ),
    //   t = k ^ (0xAA & (C-1)), C = 256>>l; leaf p = k^0xAA,
    //   V_0[k] = nck(w0[p]*x[255-p] + b0[255+p]); out = sigmoid(rw*V_8[0]+rb).
    __shared__ float  s_leafW[256];
    __shared__ float  s_leafB[256];
    __shared__ float4 s_lvl[256];   // levels 1..8: off(l)=256-2C; {w[2t+1],w[2t],b[C-1+t],0}
    {
        int k = threadIdx.x;
        int p0 = k ^ 0xAA;
        s_leafW[k] = w0[p0];
        s_leafB[k] = b0[255 + p0];
        const float* W[8] = {w1, w2, w3, w4, w5, w6, w7, w8};
        const float* B[8] = {b1, b2, b3, b4, b5, b6, b7, b8};
#pragma unroll
        for (int l = 1; l <= 8; ++l) {
            int C = 256 >> l;
            if (k < C) {
                int t = k ^ (0xAA & (C - 1));
                s_lvl[256 - 2 * C + k] =
                    make_float4(W[l-1][2*t + 1], W[l-1][2*t], B[l-1][C - 1 + t], 0.0f);
            }
        }
    }
    __syncthreads();

    float ca = __ldg(alpha) * 0.0878f;
    float cb = __ldg(beta)  * 0.129f;
    float cg = __ldg(gamma) * 2.23f;
    float ca_c = -ca * 113.68f;
    float cb_c = -cb * 69.62f;
    float rw = __ldg(root_w);
    float rb = __ldg(root_b);

    int lane   = threadIdx.x & 31;
    int warp0  = blockIdx.x * (blockDim.x >> 5) + (threadIdx.x >> 5);
    int c      = 31 - (lane ^ 21);          // x chunk for this lane
    bool loHalf = (lane < 16);

    const float4* lwv = reinterpret_cast<const float4*>(s_leafW);
    const float4* lbv = reinterpret_cast<const float4*>(s_leafB);

    if (warp0 >= rows) return;
    const int S = warp_stride;

    // Preload first pair (rowB clamped for safety; store is guarded).
    float4 loA, hiA, loB, hiB;
    {
        int rA = warp0;
        int rB = (warp0 + S < rows) ? warp0 + S : rows - 1;
        const float4* xa = reinterpret_cast<const float4*>(x + (size_t)rA * 256);
        const float4* xb = reinterpret_cast<const float4*>(x + (size_t)rB * 256);
        loA = __ldg(&xa[2*c]); hiA = __ldg(&xa[2*c + 1]);
        loB = __ldg(&xb[2*c]); hiB = __ldg(&xb[2*c + 1]);
    }

    for (int row = warp0; row < rows; row += 2 * S) {
        // ---- Level 0 (shared leaf params; elem map {hi.y,hi.x,hi.w,hi.z,lo.y,lo.x,lo.w,lo.z})
        float4 wa = lwv[2*lane], wb = lwv[2*lane + 1];
        float4 ba = lbv[2*lane], bb = lbv[2*lane + 1];

        float vA0 = nck_f(fmaf(wa.x, hiA.y, ba.x), ca, cb, cg, ca_c, cb_c);
        float vA1 = nck_f(fmaf(wa.y, hiA.x, ba.y), ca, cb, cg, ca_c, cb_c);
        float vA2 = nck_f(fmaf(wa.z, hiA.w, ba.z), ca, cb, cg, ca_c, cb_c);
        float vA3 = nck_f(fmaf(wa.w, hiA.z, ba.w), ca, cb, cg, ca_c, cb_c);
        float vA4 = nck_f(fmaf(wb.x, loA.y, bb.x), ca, cb, cg, ca_c, cb_c);
        float vA5 = nck_f(fmaf(wb.y, loA.x, bb.y), ca, cb, cg, ca_c, cb_c);
        float vA6 = nck_f(fmaf(wb.z, loA.w, bb.z), ca, cb, cg, ca_c, cb_c);
        float vA7 = nck_f(fmaf(wb.w, loA.z, bb.w), ca, cb, cg, ca_c, cb_c);

        float vB0 = nck_f(fmaf(wa.x, hiB.y, ba.x), ca, cb, cg, ca_c, cb_c);
        float vB1 = nck_f(fmaf(wa.y, hiB.x, ba.y), ca, cb, cg, ca_c, cb_c);
        float vB2 = nck_f(fmaf(wa.z, hiB.w, ba.z), ca, cb, cg, ca_c, cb_c);
        float vB3 = nck_f(fmaf(wa.w, hiB.z, ba.w), ca, cb, cg, ca_c, cb_c);
        float vB4 = nck_f(fmaf(wb.x, loB.y, bb.x), ca, cb, cg, ca_c, cb_c);
        float vB5 = nck_f(fmaf(wb.y, loB.x, bb.y), ca, cb, cg, ca_c, cb_c);
        float vB6 = nck_f(fmaf(wb.z, loB.w, bb.z), ca, cb, cg, ca_c, cb_c);
        float vB7 = nck_f(fmaf(wb.w, loB.z, bb.w), ca, cb, cg, ca_c, cb_c);

        // ---- Prefetch next pair's x (hidden under levels 1..8)
        {
            int nA = row + 2 * S;
            if (nA < rows) {
                int nB = (nA + S < rows) ? nA + S : rows - 1;
                const float4* xa = reinterpret_cast<const float4*>(x + (size_t)nA * 256);
                const float4* xb = reinterpret_cast<const float4*>(x + (size_t)nB * 256);
                loA = __ldg(&xa[2*c]); hiA = __ldg(&xa[2*c + 1]);
                loB = __ldg(&xb[2*c]); hiB = __ldg(&xb[2*c + 1]);
            }
        }

        // ---- Level 1
        float4 p;
        p = s_lvl[4*lane + 0];
        float uA0 = nck_f(fmaf(p.x, vA0, fmaf(p.y, vA1, p.z)), ca, cb, cg, ca_c, cb_c);
        float uB0 = nck_f(fmaf(p.x, vB0, fmaf(p.y, vB1, p.z)), ca, cb, cg, ca_c, cb_c);
        p = s_lvl[4*lane + 1];
        float uA1 = nck_f(fmaf(p.x, vA2, fmaf(p.y, vA3, p.z)), ca, cb, cg, ca_c, cb_c);
        float uB1 = nck_f(fmaf(p.x, vB2, fmaf(p.y, vB3, p.z)), ca, cb, cg, ca_c, cb_c);
        p = s_lvl[4*lane + 2];
        float uA2 = nck_f(fmaf(p.x, vA4, fmaf(p.y, vA5, p.z)), ca, cb, cg, ca_c, cb_c);
        float uB2 = nck_f(fmaf(p.x, vB4, fmaf(p.y, vB5, p.z)), ca, cb, cg, ca_c, cb_c);
        p = s_lvl[4*lane + 3];
        float uA3 = nck_f(fmaf(p.x, vA6, fmaf(p.y, vA7, p.z)), ca, cb, cg, ca_c, cb_c);
        float uB3 = nck_f(fmaf(p.x, vB6, fmaf(p.y, vB7, p.z)), ca, cb, cg, ca_c, cb_c);

        // ---- Level 2
        p = s_lvl[128 + 2*lane];
        float sA0 = nck_f(fmaf(p.x, uA0, fmaf(p.y, uA1, p.z)), ca, cb, cg, ca_c, cb_c);
        float sB0 = nck_f(fmaf(p.x, uB0, fmaf(p.y, uB1, p.z)), ca, cb, cg, ca_c, cb_c);
        p = s_lvl[128 + 2*lane + 1];
        float sA1 = nck_f(fmaf(p.x, uA2, fmaf(p.y, uA3, p.z)), ca, cb, cg, ca_c, cb_c);
        float sB1 = nck_f(fmaf(p.x, uB2, fmaf(p.y, uB3, p.z)), ca, cb, cg, ca_c, cb_c);

        // ---- Level 3: valA/valB = V3[lane] in all 32 lanes
        p = s_lvl[192 + lane];
        float valA = nck_f(fmaf(p.x, sA0, fmaf(p.y, sA1, p.z)), ca, cb, cg, ca_c, cb_c);
        float valB = nck_f(fmaf(p.x, sB0, fmaf(p.y, sB1, p.z)), ca, cb, cg, ca_c, cb_c);

        // ---- Level 4: pack rows. Lanes 0-15 -> row A V4[lane], lanes 16-31 -> row B V4[lane-16].
        int src0 = (2*lane) & 31, src1 = (2*lane + 1) & 31;
        float a0A = __shfl_sync(0xffffffffu, valA, src0);
        float a1A = __shfl_sync(0xffffffffu, valA, src1);
        float a0B = __shfl_sync(0xffffffffu, valB, src0);
        float a1B = __shfl_sync(0xffffffffu, valB, src1);
        float in0 = loHalf ? a0A : a0B;
        float in1 = loHalf ? a1A : a1B;
        p = s_lvl[224 + (lane & 15)];
        float val = nck_f(fmaf(p.x, in0, fmaf(p.y, in1, p.z)), ca, cb, cg, ca_c, cb_c);

        // ---- Levels 5..8: packed halves advance with the standard pattern.
        {
            float t0 = __shfl_sync(0xffffffffu, val, src0);
            float t1 = __shfl_sync(0xffffffffu, val, src1);
            p = s_lvl[240 + (lane & 7)];
            val = nck_f(fmaf(p.x, t0, fmaf(p.y, t1, p.z)), ca, cb, cg, ca_c, cb_c);
        }
        {
            float t0 = __shfl_sync(0xffffffffu, val, src0);
            float t1 = __shfl_sync(0xffffffffu, val, src1);
            p = s_lvl[248 + (lane & 3)];
            val = nck_f(fmaf(p.x, t0, fmaf(p.y, t1, p.z)), ca, cb, cg, ca_c, cb_c);
        }
        {
            float t0 = __shfl_sync(0xffffffffu, val, src0);
            float t1 = __shfl_sync(0xffffffffu, val, src1);
            p = s_lvl[252 + (lane & 1)];
            val = nck_f(fmaf(p.x, t0, fmaf(p.y, t1, p.z)), ca, cb, cg, ca_c, cb_c);
        }
        {
            float t0 = __shfl_sync(0xffffffffu, val, src0);
            float t1 = __shfl_sync(0xffffffffu, val, src1);
            p = s_lvl[254];
            val = nck_f(fmaf(p.x, t0, fmaf(p.y, t1, p.z)), ca, cb, cg, ca_c, cb_c);
        }
        // Root of row A in lane 0, row B in lane 1.
        float o   = fmaf(rw, val, rb);
        float sig = __fdividef(1.0f, 1.0f + ex2f(-1.4426950408889634f * o));
        if (lane == 0) out[row] = sig;
        else if (lane == 1 && row + S < rows) out[row + S] = sig;
    }
}

extern "C" void kernel_launch(void* const* d_in, const int* in_sizes, int n_in,
                              void* d_out, int out_size)
{
    // Grouped order: x, w0..w8, b0..b8, scalars. Interleaved order (dict):
    // x, w0, b0, w1, b1, ... Disambiguate via sizes (b has 511 elems).
    const float* x = (const float*)d_in[0];
    const float* w[9];
    const float* b[9];
    if (n_in >= 3 && in_sizes[2] == 511) {
        for (int l = 0; l < 9; ++l) { w[l] = (const float*)d_in[1 + 2*l];
                                      b[l] = (const float*)d_in[2 + 2*l]; }
    } else {
        for (int l = 0; l < 9; ++l) { w[l] = (const float*)d_in[1 + l];
                                      b[l] = (const float*)d_in[10 + l]; }
    }
    const float* alpha  = (const float*)d_in[19];
    const float* beta   = (const float*)d_in[20];
    const float* gammap = (const float*)d_in[21];
    const float* root_w = (const float*)d_in[22];
    const float* root_b = (const float*)d_in[23];
    float* out = (float*)d_out;

    int rows = in_sizes[0] / 256;          // 32768
    int warps_per_block = 256 / 32;        // 8
    int nblocks = 1024;                    // 8192 warps, 2 row-pairs per warp
    int total_warps = nblocks * warps_per_block;
    if (total_warps > rows) {
        nblocks = (rows + warps_per_block - 1) / warps_per_block;
        total_warps = nblocks * warps_per_block;
    }

    tree_kernel<<<nblocks, 256>>>(
        x, out,
        w[0], w[1], w[2], w[3], w[4], w[5], w[6], w[7], w[8],
        b[0], b[1], b[2], b[3], b[4], b[5], b[6], b[7], b[8],
        alpha, beta, gammap, root_w, root_b,
        rows, total_warps);
}